// round 13
// baseline (speedup 1.0000x reference)
#include <cuda_runtime.h>
#include <cuda_bf16.h>

// Problem constants (WordSmoothCriterion: B=4, T=2048, V=32000, NNZ=801)
#define NROWS 8192
#define VDIM  32000
#define NNZ   801
#define TAU   0.8f
#define RARE  1.0f
#define ALPHA 0.7f

#define TPB   256
#define EPT   4          // 4*256 = 1024 >= 801 (k=3 slice predicated: tid < 33)
#define GRID  592        // 148 SMs * 4 resident CTAs -> single persistent wave
#define MAXR  14         // max rows per CTA (ceil(8192/592))

// Scratch (device globals — allocation-free)
__device__ float g_smooth[NROWS];      // per-row sum(g*sim)
__device__ float g_ml[NROWS];          // per-row lp[target]*mask
__device__ float g_maskv[NROWS];       // per-row mask
__device__ unsigned int g_count = 0;   // completion counter (self-resetting)

// ---------------------------------------------------------------------------
// Persistent kernel, warp-autonomous main loop (no barriers), depth-2 cols
// pipeline. All 8 warps of a CTA walk the same row list in the same order
// (keeps L2 active-row working set small); each warp reduces its own slice
// with shuffles and drops 2 floats into smem per row.
// ---------------------------------------------------------------------------
__global__ __launch_bounds__(TPB, 4)
void ws_wa_kernel(const float* __restrict__ logp,
                  const float* __restrict__ mask,
                  const float* __restrict__ sim_values,
                  const float* __restrict__ idf_values,
                  const int*   __restrict__ target,
                  const int*   __restrict__ sim_cols,
                  float*       __restrict__ out)
{
    const int bid  = blockIdx.x;
    const int tid  = threadIdx.x;
    const int warp = tid >> 5;
    const int lane = tid & 31;
    const float inv_tau = 1.0f / TAU;
    const bool p3 = (tid < NNZ - 3 * TPB);     // k=3 slice predicate (tid < 33)

    __shared__ float s_pv[MAXR][8], s_pgv[MAXR][8];
    __shared__ bool  s_last;

    const int R = (NROWS - bid + GRID - 1) / GRID;   // 13 or 14 rows

    // ---- pipeline registers ----
    // M-stage: row i   (streams + gathers, consumed by math)
    // G-stage: row i+1 (cols -> gathers issued this iteration; streams loaded)
    // L-stage: row i+2 (cols loaded this iteration)
    int   cG[EPT], cL[EPT];
    float sM[EPT], dM[EPT], gM[EPT];
    float sG[EPT], dG[EPT], gG[EPT];

    // ---------------- prologue ----------------
    {
        const int n = bid;                       // row 0
        const int r = target[n];
        const float* sv = sim_values + (size_t)r * NNZ;
        const float* iv = idf_values + (size_t)r * NNZ;
        const int*   sc = sim_cols   + (size_t)r * NNZ;
        const float* lp = logp       + (size_t)n * VDIM;
        int c0[EPT];
        #pragma unroll
        for (int k = 0; k < EPT; k++) {
            const bool ok = (k < 3) || p3;
            const int  j  = tid + k * TPB;
            c0[k] = ok ? sc[j] : 0;
            sM[k] = ok ? sv[j] : 0.0f;
            dM[k] = ok ? iv[j] : 0.0f;
        }
        #pragma unroll
        for (int k = 0; k < EPT; k++) gM[k] = lp[c0[k]];   // one-time stall
    }
    if (R > 1) {
        const int n = bid + GRID;                // row 1 cols
        const int r = target[n];
        const int* sc = sim_cols + (size_t)r * NNZ;
        #pragma unroll
        for (int k = 0; k < EPT; k++) {
            const bool ok = (k < 3) || p3;
            cG[k] = ok ? sc[tid + k * TPB] : 0;
        }
    } else {
        #pragma unroll
        for (int k = 0; k < EPT; k++) cG[k] = 0;
    }

    // ---------------- main loop (no barriers) ----------------
    for (int i = 0; i < R; i++) {
        // 1. cols for row i+2 (arrive one full iteration before their gathers)
        if (i + 2 < R) {
            const int n = bid + (i + 2) * GRID;
            const int r = target[n];
            const int* sc = sim_cols + (size_t)r * NNZ;
            #pragma unroll
            for (int k = 0; k < EPT; k++) {
                const bool ok = (k < 3) || p3;
                cL[k] = ok ? sc[tid + k * TPB] : 0;
            }
        } else {
            #pragma unroll
            for (int k = 0; k < EPT; k++) cL[k] = 0;
        }

        // 2. streams + 3. gathers for row i+1 (cols arrived last iteration)
        if (i + 1 < R) {
            const int n = bid + (i + 1) * GRID;
            const int r = target[n];
            const float* sv = sim_values + (size_t)r * NNZ;
            const float* iv = idf_values + (size_t)r * NNZ;
            const float* lp = logp       + (size_t)n * VDIM;
            #pragma unroll
            for (int k = 0; k < EPT; k++) {
                const bool ok = (k < 3) || p3;
                const int  j  = tid + k * TPB;
                sG[k] = ok ? sv[j] : 0.0f;
                dG[k] = ok ? iv[j] : 0.0f;
            }
            #pragma unroll
            for (int k = 0; k < EPT; k++) gG[k] = lp[cG[k]];
        } else {
            #pragma unroll
            for (int k = 0; k < EPT; k++) { sG[k] = 0.0f; dG[k] = 0.0f; gG[k] = 0.0f; }
        }

        // 4. math for row i + warp-only reduction
        float sum_v = 0.0f, sum_gv = 0.0f;
        #pragma unroll
        for (int k = 0; k < EPT; k++) {
            const bool ok = (k < 3) || p3;
            float val = __expf(__expf((sM[k] - 1.0f - TAU * RARE * dM[k]) * inv_tau) * inv_tau);
            if (!ok) val = 0.0f;
            sum_v  += val;
            sum_gv += val * gM[k];
        }
        #pragma unroll
        for (int o = 16; o > 0; o >>= 1) {
            sum_v  += __shfl_down_sync(0xffffffffu, sum_v,  o);
            sum_gv += __shfl_down_sync(0xffffffffu, sum_gv, o);
        }
        if (lane == 0) { s_pv[i][warp] = sum_v; s_pgv[i][warp] = sum_gv; }

        // 5. rotate pipeline
        #pragma unroll
        for (int k = 0; k < EPT; k++) {
            sM[k] = sG[k]; dM[k] = dG[k]; gM[k] = gG[k]; cG[k] = cL[k];
        }
    }

    __syncthreads();                              // single barrier: partials ready

    // ---------------- per-CTA epilogue ----------------
    // thread t (< R) finishes row t: combine 8 warp partials (fixed order),
    // compute ml/mask terms (overlaps other CTAs' drain).
    if (tid < R) {
        const int n = bid + tid * GRID;
        float pv = 0.0f, pgv = 0.0f;
        #pragma unroll
        for (int w = 0; w < 8; w++) { pv += s_pv[tid][w]; pgv += s_pgv[tid][w]; }
        g_smooth[n] = pgv / pv;
        const int   r = target[n];
        const float m = mask[n];
        g_ml[n]    = logp[(size_t)n * VDIM + r] * m;
        g_maskv[n] = m;
        __threadfence();                          // device-scope: publish writes
    }
    __syncthreads();
    if (tid == 0) {
        unsigned int old = atomicAdd(&g_count, 1u);
        s_last = (old == (unsigned int)(GRID - 1));
    }
    __syncthreads();

    // ---------------- last CTA: final deterministic reduction ----------------
    if (s_last) {
        double d_sm = 0.0, d_ml = 0.0, d_m = 0.0;
        for (int i = tid; i < NROWS; i += TPB) {  // fixed row order
            d_sm += (double)g_smooth[i];
            d_ml += (double)g_ml[i];
            d_m  += (double)g_maskv[i];
        }
        #pragma unroll
        for (int o = 16; o > 0; o >>= 1) {
            d_sm += __shfl_down_sync(0xffffffffu, d_sm, o);
            d_ml += __shfl_down_sync(0xffffffffu, d_ml, o);
            d_m  += __shfl_down_sync(0xffffffffu, d_m,  o);
        }
        __shared__ double sh[3][8];
        if (lane == 0) { sh[0][warp] = d_sm; sh[1][warp] = d_ml; sh[2][warp] = d_m; }
        __syncthreads();
        if (warp == 0) {
            d_sm = (lane < 8) ? sh[0][lane] : 0.0;
            d_ml = (lane < 8) ? sh[1][lane] : 0.0;
            d_m  = (lane < 8) ? sh[2][lane] : 0.0;
            #pragma unroll
            for (int o = 4; o > 0; o >>= 1) {
                d_sm += __shfl_down_sync(0xffffffffu, d_sm, o);
                d_ml += __shfl_down_sync(0xffffffffu, d_ml, o);
                d_m  += __shfl_down_sync(0xffffffffu, d_m,  o);
            }
            if (lane == 0) {
                double smooth_loss = -d_sm / d_m;
                double ml_loss     = -d_ml / d_m;
                out[0] = (float)((double)ALPHA * smooth_loss
                                 + (1.0 - (double)ALPHA) * ml_loss);
                g_count = 0;                      // reset for next graph replay
            }
        }
    }
}

// ---------------------------------------------------------------------------
extern "C" void kernel_launch(void* const* d_in, const int* in_sizes, int n_in,
                              void* d_out, int out_size)
{
    const float* logp       = (const float*)d_in[0];
    const float* mask       = (const float*)d_in[1];
    const float* sim_values = (const float*)d_in[2];
    const float* idf_values = (const float*)d_in[3];
    const int*   target     = (const int*)  d_in[4];
    const int*   sim_cols   = (const int*)  d_in[5];
    float*       out        = (float*)d_out;

    ws_wa_kernel<<<GRID, TPB>>>(logp, mask, sim_values, idf_values,
                                target, sim_cols, out);
}

// round 14
// speedup vs baseline: 1.0554x; 1.0554x over previous
#include <cuda_runtime.h>
#include <cuda_bf16.h>

// Problem constants (WordSmoothCriterion: B=4, T=2048, V=32000, NNZ=801)
#define NROWS 8192
#define VDIM  32000
#define NNZ   801
#define TAU   0.8f
#define RARE  1.0f
#define ALPHA 0.7f

#define TPB  256
#define EPT  4          // 4*256 = 1024 >= 801 (k=3 slice predicated: tid < 33)
#define GRID 592        // 148 SMs * 4 resident CTAs -> single persistent wave

// Scratch (device globals — allocation-free)
__device__ float g_smooth[NROWS];      // per-row sum(g*sim)
__device__ float g_ml[NROWS];          // per-row lp[target]*mask
__device__ float g_maskv[NROWS];       // per-row mask
__device__ unsigned int g_count = 0;   // completion counter (self-resetting)

// ---------------------------------------------------------------------------
// R9 persistent pipelined kernel + depth-2 cols stage. Per-row barriers KEPT
// (CTA warps stay in lockstep on the same row -> L2 working set ~83MB).
// Gathers for row i+1 use cols loaded at iteration i-1 (full-iteration lead).
// ---------------------------------------------------------------------------
__global__ __launch_bounds__(TPB, 4)
void ws_p2_kernel(const float* __restrict__ logp,
                  const float* __restrict__ mask,
                  const float* __restrict__ sim_values,
                  const float* __restrict__ idf_values,
                  const int*   __restrict__ target,
                  const int*   __restrict__ sim_cols,
                  float*       __restrict__ out)
{
    const int bid  = blockIdx.x;
    const int tid  = threadIdx.x;
    const int warp = tid >> 5;
    const int lane = tid & 31;
    const float inv_tau = 1.0f / TAU;
    const bool p3 = (tid < NNZ - 3 * TPB);     // k=3 slice predicate (tid < 33)

    __shared__ float s_v[8], s_gv[8];
    __shared__ bool  s_last;

    const int R = (NROWS - bid + GRID - 1) / GRID;   // 13 or 14 rows

    // pipeline registers:
    //   M-stage: row i   (sM,dM,gM ready for math; mA,lprA scalars)
    //   cG: cols of row i+1 (loaded one iteration earlier)
    int   cG[EPT], cL[EPT];
    float sM[EPT], dM[EPT], gM[EPT];
    float mA = 0.0f, lprA = 0.0f;

    // ---------------- prologue: row 0 fully, row 1 cols ----------------
    {
        const int n = bid;
        const int r = target[n];
        const float* sv = sim_values + (size_t)r * NNZ;
        const float* iv = idf_values + (size_t)r * NNZ;
        const int*   sc = sim_cols   + (size_t)r * NNZ;
        const float* lp = logp       + (size_t)n * VDIM;
        int c0[EPT];
        #pragma unroll
        for (int k = 0; k < EPT; k++) {
            const bool ok = (k < 3) || p3;
            const int  j  = tid + k * TPB;
            c0[k] = ok ? sc[j] : 0;
            sM[k] = ok ? sv[j] : 0.0f;
            dM[k] = ok ? iv[j] : 0.0f;
        }
        if (tid == 0) { mA = mask[n]; lprA = lp[r]; }
        #pragma unroll
        for (int k = 0; k < EPT; k++) gM[k] = lp[c0[k]];   // one-time stall
    }
    if (R > 1) {
        const int n = bid + GRID;
        const int r = target[n];
        const int* sc = sim_cols + (size_t)r * NNZ;
        #pragma unroll
        for (int k = 0; k < EPT; k++) {
            const bool ok = (k < 3) || p3;
            cG[k] = ok ? sc[tid + k * TPB] : 0;
        }
    } else {
        #pragma unroll
        for (int k = 0; k < EPT; k++) cG[k] = 0;
    }

    // ---------------- main loop (R9 structure + depth-2 cols) ----------------
    for (int i = 0; i < R; i++) {
        const bool hn = (i + 1 < R);

        // 1. cols for row i+2 (a full iteration ahead of their gathers)
        if (i + 2 < R) {
            const int n = bid + (i + 2) * GRID;
            const int r = target[n];
            const int* sc = sim_cols + (size_t)r * NNZ;
            #pragma unroll
            for (int k = 0; k < EPT; k++) {
                const bool ok = (k < 3) || p3;
                cL[k] = ok ? sc[tid + k * TPB] : 0;
            }
        } else {
            #pragma unroll
            for (int k = 0; k < EPT; k++) cL[k] = 0;
        }

        // 2. streams + gathers for row i+1 (cols arrived last iteration -> no bubble)
        float sG[EPT], dG[EPT], gG[EPT];
        float mB = 0.0f, lprB = 0.0f;
        if (hn) {
            const int n = bid + (i + 1) * GRID;
            const int r = target[n];
            const float* sv = sim_values + (size_t)r * NNZ;
            const float* iv = idf_values + (size_t)r * NNZ;
            const float* lp = logp       + (size_t)n * VDIM;
            #pragma unroll
            for (int k = 0; k < EPT; k++) gG[k] = lp[cG[k]];   // ready cols
            #pragma unroll
            for (int k = 0; k < EPT; k++) {
                const bool ok = (k < 3) || p3;
                const int  j  = tid + k * TPB;
                sG[k] = ok ? sv[j] : 0.0f;
                dG[k] = ok ? iv[j] : 0.0f;
            }
            if (tid == 0) { mB = mask[n]; lprB = lp[r]; }
        } else {
            #pragma unroll
            for (int k = 0; k < EPT; k++) { sG[k] = 0.0f; dG[k] = 0.0f; gG[k] = 0.0f; }
        }

        // 3. math for row i
        float sum_v = 0.0f, sum_gv = 0.0f;
        #pragma unroll
        for (int k = 0; k < EPT; k++) {
            const bool ok = (k < 3) || p3;
            float val = __expf(__expf((sM[k] - 1.0f - TAU * RARE * dM[k]) * inv_tau) * inv_tau);
            if (!ok) val = 0.0f;
            sum_v  += val;
            sum_gv += val * gM[k];
        }

        // 4. block reduction (barriers kept -> warp lockstep preserved)
        #pragma unroll
        for (int o = 16; o > 0; o >>= 1) {
            sum_v  += __shfl_down_sync(0xffffffffu, sum_v,  o);
            sum_gv += __shfl_down_sync(0xffffffffu, sum_gv, o);
        }
        if (lane == 0) { s_v[warp] = sum_v; s_gv[warp] = sum_gv; }
        __syncthreads();
        if (warp == 0) {
            float a = (lane < 8) ? s_v[lane]  : 0.0f;
            float b = (lane < 8) ? s_gv[lane] : 0.0f;
            #pragma unroll
            for (int o = 4; o > 0; o >>= 1) {
                a += __shfl_down_sync(0xffffffffu, a, o);
                b += __shfl_down_sync(0xffffffffu, b, o);
            }
            if (lane == 0) {
                const int n = bid + i * GRID;
                g_smooth[n] = b / a;
                g_ml[n]     = lprA * mA;
                g_maskv[n]  = mA;
            }
        }
        __syncthreads();                          // protect s_v/s_gv reuse

        // 5. rotate pipeline
        mA = mB; lprA = lprB;
        #pragma unroll
        for (int k = 0; k < EPT; k++) {
            sM[k] = sG[k]; dM[k] = dG[k]; gM[k] = gG[k]; cG[k] = cL[k];
        }
    }

    // ---------------- completion + last-CTA final reduction ----------------
    if (tid == 0) {
        __threadfence();
        unsigned int old = atomicAdd(&g_count, 1u);
        s_last = (old == (unsigned int)(GRID - 1));
    }
    __syncthreads();

    if (s_last) {
        double d_sm = 0.0, d_ml = 0.0, d_m = 0.0;
        for (int i = tid; i < NROWS; i += TPB) {  // fixed row order -> deterministic
            d_sm += (double)g_smooth[i];
            d_ml += (double)g_ml[i];
            d_m  += (double)g_maskv[i];
        }
        #pragma unroll
        for (int o = 16; o > 0; o >>= 1) {
            d_sm += __shfl_down_sync(0xffffffffu, d_sm, o);
            d_ml += __shfl_down_sync(0xffffffffu, d_ml, o);
            d_m  += __shfl_down_sync(0xffffffffu, d_m,  o);
        }
        __shared__ double sh[3][8];
        if (lane == 0) { sh[0][warp] = d_sm; sh[1][warp] = d_ml; sh[2][warp] = d_m; }
        __syncthreads();
        if (warp == 0) {
            d_sm = (lane < 8) ? sh[0][lane] : 0.0;
            d_ml = (lane < 8) ? sh[1][lane] : 0.0;
            d_m  = (lane < 8) ? sh[2][lane] : 0.0;
            #pragma unroll
            for (int o = 4; o > 0; o >>= 1) {
                d_sm += __shfl_down_sync(0xffffffffu, d_sm, o);
                d_ml += __shfl_down_sync(0xffffffffu, d_ml, o);
                d_m  += __shfl_down_sync(0xffffffffu, d_m,  o);
            }
            if (lane == 0) {
                double smooth_loss = -d_sm / d_m;
                double ml_loss     = -d_ml / d_m;
                out[0] = (float)((double)ALPHA * smooth_loss
                                 + (1.0 - (double)ALPHA) * ml_loss);
                g_count = 0;                      // reset for next graph replay
            }
        }
    }
}

// ---------------------------------------------------------------------------
extern "C" void kernel_launch(void* const* d_in, const int* in_sizes, int n_in,
                              void* d_out, int out_size)
{
    const float* logp       = (const float*)d_in[0];
    const float* mask       = (const float*)d_in[1];
    const float* sim_values = (const float*)d_in[2];
    const float* idf_values = (const float*)d_in[3];
    const int*   target     = (const int*)  d_in[4];
    const int*   sim_cols   = (const int*)  d_in[5];
    float*       out        = (float*)d_out;

    ws_p2_kernel<<<GRID, TPB>>>(logp, mask, sim_values, idf_values,
                                target, sim_cols, out);
}

// round 15
// speedup vs baseline: 1.1464x; 1.0863x over previous
#include <cuda_runtime.h>
#include <cuda_bf16.h>

// Problem constants (WordSmoothCriterion: B=4, T=2048, V=32000, NNZ=801)
#define NROWS 8192
#define VDIM  32000
#define NNZ   801
#define TAU   0.8f
#define RARE  1.0f
#define ALPHA 0.7f

#define TPB  256
#define EPT  4          // 4*256 = 1024 >= 801 (k=3 slice predicated: tid < 33)
#define GRID 740        // 148 SMs * 5 resident CTAs -> single persistent wave

// Scratch (device globals — allocation-free)
__device__ double g_psm[GRID];
__device__ double g_pml[GRID];
__device__ double g_pm[GRID];
__device__ unsigned int g_count = 0;   // completion counter (self-resetting)

// ---------------------------------------------------------------------------
// R9 persistent pipelined kernel, unchanged structure; only occupancy bumped
// to 5 CTAs/SM (GRID=740, launch_bounds(256,5)).
// ---------------------------------------------------------------------------
__global__ __launch_bounds__(TPB, 5)
void ws_persist_kernel(const float* __restrict__ logp,
                       const float* __restrict__ mask,
                       const float* __restrict__ sim_values,
                       const float* __restrict__ idf_values,
                       const int*   __restrict__ target,
                       const int*   __restrict__ sim_cols,
                       float*       __restrict__ out)
{
    const int bid  = blockIdx.x;
    const int tid  = threadIdx.x;
    const int warp = tid >> 5;
    const int lane = tid & 31;
    const float inv_tau = 1.0f / TAU;
    const bool p3 = (tid < NNZ - 3 * TPB);      // k=3 slice predicate (tid < 33)

    __shared__ float s_v[8], s_gv[8];
    __shared__ bool  s_last;

    // per-CTA accumulators (only thread 0 updates; fixed order -> deterministic)
    double acc_sm = 0.0, acc_ml = 0.0, acc_m = 0.0;

    // ---------------- prologue: load row n = bid ----------------
    int n = bid;
    const float* lpA = logp + (size_t)n * VDIM;
    int   cA[EPT];
    float sA[EPT], dA[EPT], gA[EPT];
    float mA = 0.0f, lprA = 0.0f;
    {
        const int rA = target[n];
        const float* svA = sim_values + (size_t)rA * NNZ;
        const float* ivA = idf_values + (size_t)rA * NNZ;
        const int*   scA = sim_cols   + (size_t)rA * NNZ;
        #pragma unroll
        for (int k = 0; k < EPT; k++) {
            const bool ok = (k < 3) || p3;
            const int  j  = tid + k * TPB;
            cA[k] = ok ? scA[j] : 0;
            sA[k] = ok ? svA[j] : 0.0f;
            dA[k] = ok ? ivA[j] : 0.0f;
        }
        if (tid == 0) { mA = mask[n]; lprA = lpA[rA]; }
        #pragma unroll
        for (int k = 0; k < EPT; k++) gA[k] = lpA[cA[k]];
    }

    // ---------------- main pipelined loop ----------------
    while (true) {
        const int  n2 = n + GRID;
        const bool hn = (n2 < NROWS);

        // ---- issue next row's index/value loads ----
        int   cB[EPT];
        float sB[EPT], dB[EPT];
        float mB = 0.0f, lprB = 0.0f;
        const float* lpB = logp;                 // safe default
        if (hn) {
            lpB = logp + (size_t)n2 * VDIM;
            const int rB = target[n2];
            const float* svB = sim_values + (size_t)rB * NNZ;
            const float* ivB = idf_values + (size_t)rB * NNZ;
            const int*   scB = sim_cols   + (size_t)rB * NNZ;
            #pragma unroll
            for (int k = 0; k < EPT; k++) {
                const bool ok = (k < 3) || p3;
                const int  j  = tid + k * TPB;
                cB[k] = ok ? scB[j] : 0;
                sB[k] = ok ? svB[j] : 0.0f;
                dB[k] = ok ? ivB[j] : 0.0f;
            }
            if (tid == 0) { mB = mask[n2]; lprB = lpB[rB]; }
        } else {
            #pragma unroll
            for (int k = 0; k < EPT; k++) { cB[k] = 0; sB[k] = 0.0f; dB[k] = 0.0f; }
        }

        // ---- compute current row ----
        float sum_v = 0.0f, sum_gv = 0.0f;
        #pragma unroll
        for (int k = 0; k < EPT; k++) {
            const bool ok = (k < 3) || p3;
            float val = __expf(__expf((sA[k] - 1.0f - TAU * RARE * dA[k]) * inv_tau) * inv_tau);
            if (!ok) val = 0.0f;
            sum_v  += val;
            sum_gv += val * gA[k];
        }

        // ---- issue next row's gathers (in flight during the reduction) ----
        float gB[EPT];
        if (hn) {
            #pragma unroll
            for (int k = 0; k < EPT; k++) gB[k] = lpB[cB[k]];
        } else {
            #pragma unroll
            for (int k = 0; k < EPT; k++) gB[k] = 0.0f;
        }

        // ---- block reduction of (sum_v, sum_gv) ----
        #pragma unroll
        for (int o = 16; o > 0; o >>= 1) {
            sum_v  += __shfl_down_sync(0xffffffffu, sum_v,  o);
            sum_gv += __shfl_down_sync(0xffffffffu, sum_gv, o);
        }
        if (lane == 0) { s_v[warp] = sum_v; s_gv[warp] = sum_gv; }
        __syncthreads();
        if (warp == 0) {
            float a = (lane < 8) ? s_v[lane]  : 0.0f;
            float b = (lane < 8) ? s_gv[lane] : 0.0f;
            #pragma unroll
            for (int o = 4; o > 0; o >>= 1) {
                a += __shfl_down_sync(0xffffffffu, a, o);
                b += __shfl_down_sync(0xffffffffu, b, o);
            }
            if (lane == 0) {
                acc_sm += (double)(b / a);
                acc_ml += (double)(lprA * mA);
                acc_m  += (double)mA;
            }
        }
        __syncthreads();                        // protect s_v/s_gv reuse

        if (!hn) break;

        // ---- rotate pipeline ----
        n   = n2;
        lpA = lpB; mA = mB; lprA = lprB;
        #pragma unroll
        for (int k = 0; k < EPT; k++) {
            cA[k] = cB[k]; sA[k] = sB[k]; dA[k] = dB[k]; gA[k] = gB[k];
        }
    }

    // ---------------- write per-CTA partials, last CTA finishes ----------------
    if (tid == 0) {
        g_psm[bid] = acc_sm;
        g_pml[bid] = acc_ml;
        g_pm[bid]  = acc_m;
        __threadfence();
        unsigned int old = atomicAdd(&g_count, 1u);
        s_last = (old == (unsigned int)(GRID - 1));
    }
    __syncthreads();

    if (s_last) {
        double d_sm = 0.0, d_ml = 0.0, d_m = 0.0;
        for (int i = tid; i < GRID; i += TPB) {   // fixed order -> deterministic
            d_sm += g_psm[i];
            d_ml += g_pml[i];
            d_m  += g_pm[i];
        }
        #pragma unroll
        for (int o = 16; o > 0; o >>= 1) {
            d_sm += __shfl_down_sync(0xffffffffu, d_sm, o);
            d_ml += __shfl_down_sync(0xffffffffu, d_ml, o);
            d_m  += __shfl_down_sync(0xffffffffu, d_m,  o);
        }
        __shared__ double sh[3][8];
        if (lane == 0) { sh[0][warp] = d_sm; sh[1][warp] = d_ml; sh[2][warp] = d_m; }
        __syncthreads();
        if (warp == 0) {
            d_sm = (lane < 8) ? sh[0][lane] : 0.0;
            d_ml = (lane < 8) ? sh[1][lane] : 0.0;
            d_m  = (lane < 8) ? sh[2][lane] : 0.0;
            #pragma unroll
            for (int o = 4; o > 0; o >>= 1) {
                d_sm += __shfl_down_sync(0xffffffffu, d_sm, o);
                d_ml += __shfl_down_sync(0xffffffffu, d_ml, o);
                d_m  += __shfl_down_sync(0xffffffffu, d_m,  o);
            }
            if (lane == 0) {
                double smooth_loss = -d_sm / d_m;
                double ml_loss     = -d_ml / d_m;
                out[0] = (float)((double)ALPHA * smooth_loss
                                 + (1.0 - (double)ALPHA) * ml_loss);
                g_count = 0;   // reset for next graph replay
            }
        }
    }
}

// ---------------------------------------------------------------------------
extern "C" void kernel_launch(void* const* d_in, const int* in_sizes, int n_in,
                              void* d_out, int out_size)
{
    const float* logp       = (const float*)d_in[0];
    const float* mask       = (const float*)d_in[1];
    const float* sim_values = (const float*)d_in[2];
    const float* idf_values = (const float*)d_in[3];
    const int*   target     = (const int*)  d_in[4];
    const int*   sim_cols   = (const int*)  d_in[5];
    float*       out        = (float*)d_out;

    ws_persist_kernel<<<GRID, TPB>>>(logp, mask, sim_values, idf_values,
                                     target, sim_cols, out);
}